// round 3
// baseline (speedup 1.0000x reference)
#include <cuda_runtime.h>

#define Bb 16
#define Nn 512
#define Tt 24
#define Dd 64
#define Ee 64
#define Hh 64

// E2 scratch, k-major [B,T,E,N]
__device__ float g_e2t[Bb * Tt * Ee * Nn];

typedef unsigned long long ull;

// ---------- helpers ----------
__device__ __forceinline__ ull dup2(float a) {
    ull r;
    asm("mov.b64 %0, {%1, %1};" : "=l"(r) : "f"(a));
    return r;
}
__device__ __forceinline__ void fma2(ull& c, ull a, ull b) {
    asm("fma.rn.f32x2 %0, %1, %2, %0;" : "+l"(c) : "l"(a), "l"(b));
}
__device__ __forceinline__ float2 unpk(ull v) {
    float2 r;
    asm("mov.b64 {%0, %1}, %2;" : "=f"(r.x), "=f"(r.y) : "l"(v));
    return r;
}
__device__ __forceinline__ void cp16(float* s, const float* g) {
    unsigned int sa = (unsigned int)__cvta_generic_to_shared(s);
    asm volatile("cp.async.cg.shared.global [%0], [%1], 16;" ::"r"(sa), "l"(g));
}
__device__ __forceinline__ void cp_commit() { asm volatile("cp.async.commit_group;"); }
template <int N>
__device__ __forceinline__ void cp_wait() {
    asm volatile("cp.async.wait_group %0;" ::"n"(N));
}

// ============================================================================
// Kernel P: E2^T = (x@W2+b2)^T stored k-major [B,T,E,N].
// grid = B*T*2 (n-halves of 256), 256 threads, 4 row-tiles per block.
// ============================================================================
__global__ void __launch_bounds__(256, 2)
gcn_proj(const float* __restrict__ x, const float* __restrict__ W2,
         const float* __restrict__ b2) {
    extern __shared__ float sm[];
    float* W2s = sm;          // 4096
    float* xs0 = sm + 4096;   // 64*68
    float* xs1 = sm + 8448;   // 64*68
    float* et  = sm + 12800;  // 64*68
    float* b2s = sm + 17152;  // 64

    const int tid = threadIdx.x;
    const int blk = blockIdx.x;
    const int half = blk & 1;
    const int bt = blk >> 1;
    const int t = bt % Tt, b = bt / Tt;
    const int nbase = half * 256;
    const float* xg = x + ((size_t)b * Nn * Tt + t) * Dd;

    // prologue: x tiles 0,1 via cp.async
#pragma unroll
    for (int i = 0; i < 4; i++) {
        int ch = tid + 256 * i, row = ch >> 4, col = (ch & 15) * 4;
        cp16(&xs0[row * 68 + col], &xg[(size_t)(nbase + row) * (Tt * Dd) + col]);
    }
    cp_commit();
#pragma unroll
    for (int i = 0; i < 4; i++) {
        int ch = tid + 256 * i, row = ch >> 4, col = (ch & 15) * 4;
        cp16(&xs1[row * 68 + col], &xg[(size_t)(nbase + 64 + row) * (Tt * Dd) + col]);
    }
    cp_commit();
#pragma unroll
    for (int i = 0; i < 16; i++) W2s[tid + 256 * i] = W2[tid + 256 * i];
    if (tid < 64) b2s[tid] = b2[tid];

    const int r = tid >> 2;
    const int e0 = (tid & 3) * 16;

    for (int tl = 0; tl < 4; tl++) {
        if (tl < 3) cp_wait<1>(); else cp_wait<0>();
        __syncthreads();
        const float* xs = (tl & 1) ? xs1 : xs0;

        ull acc[8];
#pragma unroll
        for (int j = 0; j < 4; j++) {
            ulonglong2 bb = *(const ulonglong2*)&b2s[e0 + 4 * j];
            acc[2 * j] = bb.x; acc[2 * j + 1] = bb.y;
        }
#pragma unroll 8
        for (int k = 0; k < 64; k++) {
            ull xd = dup2(xs[r * 68 + k]);
#pragma unroll
            for (int j = 0; j < 4; j++) {
                ulonglong2 wv = *(const ulonglong2*)&W2s[k * 64 + e0 + 4 * j];
                fma2(acc[2 * j], xd, wv.x);
                fma2(acc[2 * j + 1], xd, wv.y);
            }
        }
#pragma unroll
        for (int j = 0; j < 4; j++) {
            float2 p0 = unpk(acc[2 * j]), p1 = unpk(acc[2 * j + 1]);
            et[(e0 + 4 * j + 0) * 68 + r] = p0.x;
            et[(e0 + 4 * j + 1) * 68 + r] = p0.y;
            et[(e0 + 4 * j + 2) * 68 + r] = p1.x;
            et[(e0 + 4 * j + 3) * 68 + r] = p1.y;
        }
        __syncthreads();
        {
            float* gout = g_e2t + (size_t)(b * Tt + t) * Ee * Nn + nbase + tl * 64;
            const int e = tid >> 2, q = tid & 3;
#pragma unroll
            for (int i = 0; i < 4; i++)
                *(float4*)&gout[(size_t)e * Nn + q * 16 + 4 * i] =
                    *(const float4*)&et[e * 68 + q * 16 + 4 * i];
        }
        __syncthreads();
        if (tl + 2 < 4) {
            float* xd_ = (tl & 1) ? xs1 : xs0;
#pragma unroll
            for (int i = 0; i < 4; i++) {
                int ch = tid + 256 * i, row = ch >> 4, col = (ch & 15) * 4;
                cp16(&xd_[row * 68 + col],
                     &xg[(size_t)(nbase + (tl + 2) * 64 + row) * (Tt * Dd) + col]);
            }
            cp_commit();
        }
    }
}

// ============================================================================
// Kernel M: per (b,t,i-tile): E1=x_i@W1+b1; stream j-tiles:
//   S=E1 E2^T, P=exp(relu(S)) (max-free), H += P X; then out=relu(H/rs @ W + b)
// grid = B*T*8, 256 threads, 2 CTAs/SM.
// ============================================================================
__global__ void __launch_bounds__(256, 2)
gcn_main(const float* __restrict__ x, const float* __restrict__ W1,
         const float* __restrict__ b1, const float* __restrict__ W,
         const float* __restrict__ bias, float* __restrict__ out) {
    extern __shared__ float sm[];
    float* e1s = sm;           // 4352  [e*68 + r] (E1 transposed)
    float* xb0 = sm + 4352;    // 4096
    float* xb1 = sm + 8448;    // 4096
    float* eb0 = sm + 12544;   // 4096 (also W in phase 4)
    float* eb1 = sm + 16640;   // 4096
    float* Pt  = sm + 20736;   // 6144 swizzled [j] rows stride 96 (also W1 staging, H^T)
    float* bs1 = sm + 26880;   // 64
    float* bsO = sm + 26944;   // 64   (total 27008 floats)

    const int tid = threadIdx.x;
    const int blk = blockIdx.x;
    const int it = blk & 7, bt = blk >> 3;
    const int t = bt % Tt, b = bt / Tt;
    const int i0 = it * 64;

    const float* e2g = g_e2t + (size_t)(b * Tt + t) * Ee * Nn;
    const float* xg = x + ((size_t)b * Nn * Tt + t) * Dd;

    const int ridx = tid >> 4, cidx = tid & 15;
    const int r0 = ridx * 4, c0 = cidx * 4;

    // G1: x_i -> xb0, W1 -> Pt(stride 64), biases
#pragma unroll
    for (int i = 0; i < 4; i++) {
        int ch = tid + 256 * i, row = ch >> 4, col = (ch & 15) * 4;
        cp16(&xb0[row * 64 + col], &xg[(size_t)(i0 + row) * (Tt * Dd) + col]);
    }
#pragma unroll
    for (int i = 0; i < 4; i++) {
        int ch = tid + 256 * i;
        cp16(&Pt[ch * 4], &W1[ch * 4]);
    }
    if (tid < 16) cp16(&bs1[tid * 4], &b1[tid * 4]);
    else if (tid < 32) cp16(&bsO[(tid - 16) * 4], &bias[(tid - 16) * 4]);
    cp_commit();
    // G2: e2_0 -> eb0, x_0 -> xb1
#pragma unroll
    for (int i = 0; i < 4; i++) {
        int ch = tid + 256 * i, row = ch >> 4, col = (ch & 15) * 4;
        cp16(&eb0[row * 64 + col], &e2g[row * Nn + col]);
        cp16(&xb1[row * 64 + col], &xg[(size_t)row * (Tt * Dd) + col]);
    }
    cp_commit();
    cp_wait<1>();
    __syncthreads();

    // ---- E1 = x_i @ W1 + b1  -> e1s transposed (stride 68) ----
    {
        ull a1[4][2];
        ulonglong2 bb = *(const ulonglong2*)&bs1[c0];
#pragma unroll
        for (int u = 0; u < 4; u++) { a1[u][0] = bb.x; a1[u][1] = bb.y; }
#pragma unroll 8
        for (int d = 0; d < 64; d++) {
            ulonglong2 wv = *(const ulonglong2*)&Pt[d * 64 + c0];
#pragma unroll
            for (int u = 0; u < 4; u++) {
                ull ad = dup2(xb0[(r0 + u) * 64 + d]);
                fma2(a1[u][0], ad, wv.x);
                fma2(a1[u][1], ad, wv.y);
            }
        }
#pragma unroll
        for (int u = 0; u < 4; u++) {
            float2 p0 = unpk(a1[u][0]), p1 = unpk(a1[u][1]);
            e1s[(c0 + 0) * 68 + r0 + u] = p0.x;
            e1s[(c0 + 1) * 68 + r0 + u] = p0.y;
            e1s[(c0 + 2) * 68 + r0 + u] = p1.x;
            e1s[(c0 + 3) * 68 + r0 + u] = p1.y;
        }
    }
    __syncthreads();

    float rsp[4] = {0.f, 0.f, 0.f, 0.f};
    ull acc3[4][2];
#pragma unroll
    for (int u = 0; u < 4; u++) { acc3[u][0] = 0ull; acc3[u][1] = 0ull; }

    const int pb = c0 * 96 + (cidx & 7) * 4 + r0;  // swizzled transposed-store base

    for (int jt = 0; jt < 8; jt++) {
        // prefetch next tiles (or W on last iter)
        if (jt < 7) {
            const float* e2s_ = e2g + (jt + 1) * 64;
            float* ed = ((jt + 1) & 1) ? eb1 : eb0;
            float* xd = (jt & 1) ? xb1 : xb0;
#pragma unroll
            for (int i = 0; i < 4; i++) {
                int ch = tid + 256 * i, row = ch >> 4, col = (ch & 15) * 4;
                cp16(&ed[row * 64 + col], &e2s_[row * Nn + col]);
                cp16(&xd[row * 64 + col],
                     &xg[(size_t)((jt + 1) * 64 + row) * (Tt * Dd) + col]);
            }
            cp_commit();
        } else {
#pragma unroll
            for (int i = 0; i < 4; i++) {
                int ch = tid + 256 * i;
                cp16(&eb0[ch * 4], &W[ch * 4]);
            }
            cp_commit();
        }
        cp_wait<1>();
        __syncthreads();

        // ---- GEMM1: S-tile = E1 E2^T ----
        const float* ec = (jt & 1) ? eb1 : eb0;
        ull acc[4][2];
#pragma unroll
        for (int u = 0; u < 4; u++) { acc[u][0] = 0ull; acc[u][1] = 0ull; }
#pragma unroll 8
        for (int e = 0; e < 64; e++) {
            float4 a4 = *(const float4*)&e1s[e * 68 + r0];
            ulonglong2 bv = *(const ulonglong2*)&ec[e * 64 + c0];
            ull d0 = dup2(a4.x), d1 = dup2(a4.y), d2 = dup2(a4.z), d3 = dup2(a4.w);
            fma2(acc[0][0], d0, bv.x); fma2(acc[0][1], d0, bv.y);
            fma2(acc[1][0], d1, bv.x); fma2(acc[1][1], d1, bv.y);
            fma2(acc[2][0], d2, bv.x); fma2(acc[2][1], d2, bv.y);
            fma2(acc[3][0], d3, bv.x); fma2(acc[3][1], d3, bv.y);
        }
        // ---- exp(relu(s)) (max-free), partial row sums, transposed P store ----
        float pv[4][4];
#pragma unroll
        for (int u = 0; u < 4; u++) {
            float2 p0 = unpk(acc[u][0]), p1 = unpk(acc[u][1]);
            pv[u][0] = __expf(fminf(fmaxf(p0.x, 0.f), 80.f));
            pv[u][1] = __expf(fminf(fmaxf(p0.y, 0.f), 80.f));
            pv[u][2] = __expf(fminf(fmaxf(p1.x, 0.f), 80.f));
            pv[u][3] = __expf(fminf(fmaxf(p1.y, 0.f), 80.f));
            rsp[u] += (pv[u][0] + pv[u][1]) + (pv[u][2] + pv[u][3]);
        }
#pragma unroll
        for (int v = 0; v < 4; v++)
            *(float4*)&Pt[pb + v * 96] =
                make_float4(pv[0][v], pv[1][v], pv[2][v], pv[3][v]);
        __syncthreads();

        // ---- GEMM2: H += P X ----
        const float* xc = (jt & 1) ? xb0 : xb1;
#pragma unroll 8
        for (int jj = 0; jj < 64; jj++) {
            float4 a4 = *(const float4*)&Pt[jj * 96 + ((jj >> 2) & 7) * 4 + r0];
            ulonglong2 xv = *(const ulonglong2*)&xc[jj * 64 + c0];
            ull d0 = dup2(a4.x), d1 = dup2(a4.y), d2 = dup2(a4.z), d3 = dup2(a4.w);
            fma2(acc3[0][0], d0, xv.x); fma2(acc3[0][1], d0, xv.y);
            fma2(acc3[1][0], d1, xv.x); fma2(acc3[1][1], d1, xv.y);
            fma2(acc3[2][0], d2, xv.x); fma2(acc3[2][1], d2, xv.y);
            fma2(acc3[3][0], d3, xv.x); fma2(acc3[3][1], d3, xv.y);
        }
        __syncthreads();
    }

    // ---- finalize row sums (16-lane butterfly; lanes share rows) ----
#pragma unroll
    for (int u = 0; u < 4; u++) {
#pragma unroll
        for (int o = 1; o < 16; o <<= 1)
            rsp[u] += __shfl_xor_sync(0xffffffffu, rsp[u], o);
        rsp[u] = 1.f / rsp[u];
    }
    // ---- H normalized -> Pt transposed ----
    {
        float hv[4][4];
#pragma unroll
        for (int u = 0; u < 4; u++) {
            float2 p0 = unpk(acc3[u][0]), p1 = unpk(acc3[u][1]);
            hv[u][0] = p0.x * rsp[u]; hv[u][1] = p0.y * rsp[u];
            hv[u][2] = p1.x * rsp[u]; hv[u][3] = p1.y * rsp[u];
        }
#pragma unroll
        for (int v = 0; v < 4; v++)
            *(float4*)&Pt[pb + v * 96] =
                make_float4(hv[0][v], hv[1][v], hv[2][v], hv[3][v]);
    }
    cp_wait<0>();
    __syncthreads();

    // ---- phase 4: out = relu(H W + b) ----
    ull a4c[4][2];
    {
        ulonglong2 bo = *(const ulonglong2*)&bsO[c0];
#pragma unroll
        for (int u = 0; u < 4; u++) { a4c[u][0] = bo.x; a4c[u][1] = bo.y; }
    }
#pragma unroll 8
    for (int d = 0; d < 64; d++) {
        float4 a4 = *(const float4*)&Pt[d * 96 + ((d >> 2) & 7) * 4 + r0];
        ulonglong2 wv = *(const ulonglong2*)&eb0[d * 64 + c0];
        ull d0 = dup2(a4.x), d1 = dup2(a4.y), d2 = dup2(a4.z), d3 = dup2(a4.w);
        fma2(a4c[0][0], d0, wv.x); fma2(a4c[0][1], d0, wv.y);
        fma2(a4c[1][0], d1, wv.x); fma2(a4c[1][1], d1, wv.y);
        fma2(a4c[2][0], d2, wv.x); fma2(a4c[2][1], d2, wv.y);
        fma2(a4c[3][0], d3, wv.x); fma2(a4c[3][1], d3, wv.y);
    }
#pragma unroll
    for (int u = 0; u < 4; u++) {
        float2 p0 = unpk(a4c[u][0]), p1 = unpk(a4c[u][1]);
        float4 o = make_float4(fmaxf(p0.x, 0.f), fmaxf(p0.y, 0.f),
                               fmaxf(p1.x, 0.f), fmaxf(p1.y, 0.f));
        *(float4*)&out[((size_t)(b * Nn + i0 + r0 + u) * Tt + t) * Hh + c0] = o;
    }
}

// ============================================================================
extern "C" void kernel_launch(void* const* d_in, const int* in_sizes, int n_in,
                              void* d_out, int out_size) {
    const float* x  = (const float*)d_in[0];
    const float* W1 = (const float*)d_in[1];
    const float* b1 = (const float*)d_in[2];
    const float* W2 = (const float*)d_in[3];
    const float* b2 = (const float*)d_in[4];
    const float* W  = (const float*)d_in[5];
    const float* bias = (const float*)d_in[6];
    float* out = (float*)d_out;

    const int smemP = 17216 * 4;  // 68,864 B
    const int smemM = 27008 * 4;  // 108,032 B
    cudaFuncSetAttribute(gcn_proj, cudaFuncAttributeMaxDynamicSharedMemorySize, smemP);
    cudaFuncSetAttribute(gcn_main, cudaFuncAttributeMaxDynamicSharedMemorySize, smemM);

    gcn_proj<<<Bb * Tt * 2, 256, smemP>>>(x, W2, b2);
    gcn_main<<<Bb * Tt * 8, 256, smemM>>>(x, W1, b1, W, bias, out);
}

// round 4
// speedup vs baseline: 1.0014x; 1.0014x over previous
#include <cuda_runtime.h>

#define Bb 16
#define Nn 512
#define Tt 24
#define Dd 64
#define Ee 64
#define Hh 64

// E2 scratch, k-major [B,T,E,N]
__device__ float g_e2t[Bb * Tt * Ee * Nn];

typedef unsigned long long ull;

// ---------- helpers ----------
__device__ __forceinline__ ull dup2(float a) {
    ull r;
    asm("mov.b64 %0, {%1, %1};" : "=l"(r) : "f"(a));
    return r;
}
__device__ __forceinline__ void fma2(ull& c, ull a, ull b) {
    asm("fma.rn.f32x2 %0, %1, %2, %0;" : "+l"(c) : "l"(a), "l"(b));
}
__device__ __forceinline__ float2 unpk(ull v) {
    float2 r;
    asm("mov.b64 {%0, %1}, %2;" : "=f"(r.x), "=f"(r.y) : "l"(v));
    return r;
}
__device__ __forceinline__ void cp16(float* s, const float* g) {
    unsigned int sa = (unsigned int)__cvta_generic_to_shared(s);
    asm volatile("cp.async.cg.shared.global [%0], [%1], 16;" ::"r"(sa), "l"(g));
}
__device__ __forceinline__ void cp_commit() { asm volatile("cp.async.commit_group;"); }
template <int N>
__device__ __forceinline__ void cp_wait() {
    asm volatile("cp.async.wait_group %0;" ::"n"(N));
}

// ============================================================================
// Kernel P: E2^T = (x@W2+b2)^T stored k-major [B,T,E,N].
// grid = B*T*2 (n-halves of 256), 256 threads, 4 row-tiles per block.
// ============================================================================
__global__ void __launch_bounds__(256, 2)
gcn_proj(const float* __restrict__ x, const float* __restrict__ W2,
         const float* __restrict__ b2) {
    extern __shared__ float sm[];
    float* W2s = sm;          // 4096
    float* xs0 = sm + 4096;   // 64*68
    float* xs1 = sm + 8448;   // 64*68
    float* et  = sm + 12800;  // 64*68
    float* b2s = sm + 17152;  // 64

    const int tid = threadIdx.x;
    const int blk = blockIdx.x;
    const int half = blk & 1;
    const int bt = blk >> 1;
    const int t = bt % Tt, b = bt / Tt;
    const int nbase = half * 256;
    const float* xg = x + ((size_t)b * Nn * Tt + t) * Dd;

    // prologue: x tiles 0,1 via cp.async
#pragma unroll
    for (int i = 0; i < 4; i++) {
        int ch = tid + 256 * i, row = ch >> 4, col = (ch & 15) * 4;
        cp16(&xs0[row * 68 + col], &xg[(size_t)(nbase + row) * (Tt * Dd) + col]);
    }
    cp_commit();
#pragma unroll
    for (int i = 0; i < 4; i++) {
        int ch = tid + 256 * i, row = ch >> 4, col = (ch & 15) * 4;
        cp16(&xs1[row * 68 + col], &xg[(size_t)(nbase + 64 + row) * (Tt * Dd) + col]);
    }
    cp_commit();
#pragma unroll
    for (int i = 0; i < 16; i++) W2s[tid + 256 * i] = W2[tid + 256 * i];
    if (tid < 64) b2s[tid] = b2[tid];

    const int r = tid >> 2;
    const int e0 = (tid & 3) * 16;

    for (int tl = 0; tl < 4; tl++) {
        if (tl < 3) cp_wait<1>(); else cp_wait<0>();
        __syncthreads();
        const float* xs = (tl & 1) ? xs1 : xs0;

        ull acc[8];
#pragma unroll
        for (int j = 0; j < 4; j++) {
            ulonglong2 bb = *(const ulonglong2*)&b2s[e0 + 4 * j];
            acc[2 * j] = bb.x; acc[2 * j + 1] = bb.y;
        }
#pragma unroll 8
        for (int k = 0; k < 64; k++) {
            ull xd = dup2(xs[r * 68 + k]);
#pragma unroll
            for (int j = 0; j < 4; j++) {
                ulonglong2 wv = *(const ulonglong2*)&W2s[k * 64 + e0 + 4 * j];
                fma2(acc[2 * j], xd, wv.x);
                fma2(acc[2 * j + 1], xd, wv.y);
            }
        }
#pragma unroll
        for (int j = 0; j < 4; j++) {
            float2 p0 = unpk(acc[2 * j]), p1 = unpk(acc[2 * j + 1]);
            et[(e0 + 4 * j + 0) * 68 + r] = p0.x;
            et[(e0 + 4 * j + 1) * 68 + r] = p0.y;
            et[(e0 + 4 * j + 2) * 68 + r] = p1.x;
            et[(e0 + 4 * j + 3) * 68 + r] = p1.y;
        }
        __syncthreads();
        {
            float* gout = g_e2t + (size_t)(b * Tt + t) * Ee * Nn + nbase + tl * 64;
            const int e = tid >> 2, q = tid & 3;
#pragma unroll
            for (int i = 0; i < 4; i++)
                *(float4*)&gout[(size_t)e * Nn + q * 16 + 4 * i] =
                    *(const float4*)&et[e * 68 + q * 16 + 4 * i];
        }
        __syncthreads();
        if (tl + 2 < 4) {
            float* xd_ = (tl & 1) ? xs1 : xs0;
#pragma unroll
            for (int i = 0; i < 4; i++) {
                int ch = tid + 256 * i, row = ch >> 4, col = (ch & 15) * 4;
                cp16(&xd_[row * 68 + col],
                     &xg[(size_t)(nbase + (tl + 2) * 64 + row) * (Tt * Dd) + col]);
            }
            cp_commit();
        }
    }
}

// ============================================================================
// Kernel M: per (b,t,i-tile): E1=x_i@W1+b1; stream j-tiles:
//   S=E1 E2^T, P=exp(relu(S)) (max-free), H += P X; then out=relu(H/rs @ W + b)
// grid = B*T*8, 256 threads, 2 CTAs/SM.
// ============================================================================
__global__ void __launch_bounds__(256, 2)
gcn_main(const float* __restrict__ x, const float* __restrict__ W1,
         const float* __restrict__ b1, const float* __restrict__ W,
         const float* __restrict__ bias, float* __restrict__ out) {
    extern __shared__ float sm[];
    float* e1s = sm;           // 4352  [e*68 + r] (E1 transposed)
    float* xb0 = sm + 4352;    // 4096
    float* xb1 = sm + 8448;    // 4096
    float* eb0 = sm + 12544;   // 4096 (also W in phase 4)
    float* eb1 = sm + 16640;   // 4096
    float* Pt  = sm + 20736;   // 6144 swizzled [j] rows stride 96 (also W1 staging, H^T)
    float* bs1 = sm + 26880;   // 64
    float* bsO = sm + 26944;   // 64   (total 27008 floats)

    const int tid = threadIdx.x;
    const int blk = blockIdx.x;
    const int it = blk & 7, bt = blk >> 3;
    const int t = bt % Tt, b = bt / Tt;
    const int i0 = it * 64;

    const float* e2g = g_e2t + (size_t)(b * Tt + t) * Ee * Nn;
    const float* xg = x + ((size_t)b * Nn * Tt + t) * Dd;

    const int ridx = tid >> 4, cidx = tid & 15;
    const int r0 = ridx * 4, c0 = cidx * 4;

    // G1: x_i -> xb0, W1 -> Pt(stride 64), biases
#pragma unroll
    for (int i = 0; i < 4; i++) {
        int ch = tid + 256 * i, row = ch >> 4, col = (ch & 15) * 4;
        cp16(&xb0[row * 64 + col], &xg[(size_t)(i0 + row) * (Tt * Dd) + col]);
    }
#pragma unroll
    for (int i = 0; i < 4; i++) {
        int ch = tid + 256 * i;
        cp16(&Pt[ch * 4], &W1[ch * 4]);
    }
    if (tid < 16) cp16(&bs1[tid * 4], &b1[tid * 4]);
    else if (tid < 32) cp16(&bsO[(tid - 16) * 4], &bias[(tid - 16) * 4]);
    cp_commit();
    // G2: e2_0 -> eb0, x_0 -> xb1
#pragma unroll
    for (int i = 0; i < 4; i++) {
        int ch = tid + 256 * i, row = ch >> 4, col = (ch & 15) * 4;
        cp16(&eb0[row * 64 + col], &e2g[row * Nn + col]);
        cp16(&xb1[row * 64 + col], &xg[(size_t)row * (Tt * Dd) + col]);
    }
    cp_commit();
    cp_wait<1>();
    __syncthreads();

    // ---- E1 = x_i @ W1 + b1  -> e1s transposed (stride 68) ----
    {
        ull a1[4][2];
        ulonglong2 bb = *(const ulonglong2*)&bs1[c0];
#pragma unroll
        for (int u = 0; u < 4; u++) { a1[u][0] = bb.x; a1[u][1] = bb.y; }
#pragma unroll 8
        for (int d = 0; d < 64; d++) {
            ulonglong2 wv = *(const ulonglong2*)&Pt[d * 64 + c0];
#pragma unroll
            for (int u = 0; u < 4; u++) {
                ull ad = dup2(xb0[(r0 + u) * 64 + d]);
                fma2(a1[u][0], ad, wv.x);
                fma2(a1[u][1], ad, wv.y);
            }
        }
#pragma unroll
        for (int u = 0; u < 4; u++) {
            float2 p0 = unpk(a1[u][0]), p1 = unpk(a1[u][1]);
            e1s[(c0 + 0) * 68 + r0 + u] = p0.x;
            e1s[(c0 + 1) * 68 + r0 + u] = p0.y;
            e1s[(c0 + 2) * 68 + r0 + u] = p1.x;
            e1s[(c0 + 3) * 68 + r0 + u] = p1.y;
        }
    }
    __syncthreads();

    float rsp[4] = {0.f, 0.f, 0.f, 0.f};
    ull acc3[4][2];
#pragma unroll
    for (int u = 0; u < 4; u++) { acc3[u][0] = 0ull; acc3[u][1] = 0ull; }

    const int pb = c0 * 96 + (cidx & 7) * 4 + r0;  // swizzled transposed-store base

    for (int jt = 0; jt < 8; jt++) {
        // prefetch next tiles (or W on last iter)
        if (jt < 7) {
            const float* e2s_ = e2g + (jt + 1) * 64;
            float* ed = ((jt + 1) & 1) ? eb1 : eb0;
            float* xd = (jt & 1) ? xb1 : xb0;
#pragma unroll
            for (int i = 0; i < 4; i++) {
                int ch = tid + 256 * i, row = ch >> 4, col = (ch & 15) * 4;
                cp16(&ed[row * 64 + col], &e2s_[row * Nn + col]);
                cp16(&xd[row * 64 + col],
                     &xg[(size_t)((jt + 1) * 64 + row) * (Tt * Dd) + col]);
            }
            cp_commit();
        } else {
#pragma unroll
            for (int i = 0; i < 4; i++) {
                int ch = tid + 256 * i;
                cp16(&eb0[ch * 4], &W[ch * 4]);
            }
            cp_commit();
        }
        cp_wait<1>();
        __syncthreads();

        // ---- GEMM1: S-tile = E1 E2^T ----
        const float* ec = (jt & 1) ? eb1 : eb0;
        ull acc[4][2];
#pragma unroll
        for (int u = 0; u < 4; u++) { acc[u][0] = 0ull; acc[u][1] = 0ull; }
#pragma unroll 8
        for (int e = 0; e < 64; e++) {
            float4 a4 = *(const float4*)&e1s[e * 68 + r0];
            ulonglong2 bv = *(const ulonglong2*)&ec[e * 64 + c0];
            ull d0 = dup2(a4.x), d1 = dup2(a4.y), d2 = dup2(a4.z), d3 = dup2(a4.w);
            fma2(acc[0][0], d0, bv.x); fma2(acc[0][1], d0, bv.y);
            fma2(acc[1][0], d1, bv.x); fma2(acc[1][1], d1, bv.y);
            fma2(acc[2][0], d2, bv.x); fma2(acc[2][1], d2, bv.y);
            fma2(acc[3][0], d3, bv.x); fma2(acc[3][1], d3, bv.y);
        }
        // ---- exp(relu(s)) (max-free), partial row sums, transposed P store ----
        float pv[4][4];
#pragma unroll
        for (int u = 0; u < 4; u++) {
            float2 p0 = unpk(acc[u][0]), p1 = unpk(acc[u][1]);
            pv[u][0] = __expf(fminf(fmaxf(p0.x, 0.f), 80.f));
            pv[u][1] = __expf(fminf(fmaxf(p0.y, 0.f), 80.f));
            pv[u][2] = __expf(fminf(fmaxf(p1.x, 0.f), 80.f));
            pv[u][3] = __expf(fminf(fmaxf(p1.y, 0.f), 80.f));
            rsp[u] += (pv[u][0] + pv[u][1]) + (pv[u][2] + pv[u][3]);
        }
#pragma unroll
        for (int v = 0; v < 4; v++)
            *(float4*)&Pt[pb + v * 96] =
                make_float4(pv[0][v], pv[1][v], pv[2][v], pv[3][v]);
        __syncthreads();

        // ---- GEMM2: H += P X ----
        const float* xc = (jt & 1) ? xb0 : xb1;
#pragma unroll 8
        for (int jj = 0; jj < 64; jj++) {
            float4 a4 = *(const float4*)&Pt[jj * 96 + ((jj >> 2) & 7) * 4 + r0];
            ulonglong2 xv = *(const ulonglong2*)&xc[jj * 64 + c0];
            ull d0 = dup2(a4.x), d1 = dup2(a4.y), d2 = dup2(a4.z), d3 = dup2(a4.w);
            fma2(acc3[0][0], d0, xv.x); fma2(acc3[0][1], d0, xv.y);
            fma2(acc3[1][0], d1, xv.x); fma2(acc3[1][1], d1, xv.y);
            fma2(acc3[2][0], d2, xv.x); fma2(acc3[2][1], d2, xv.y);
            fma2(acc3[3][0], d3, xv.x); fma2(acc3[3][1], d3, xv.y);
        }
        __syncthreads();
    }

    // ---- finalize row sums (16-lane butterfly; lanes share rows) ----
#pragma unroll
    for (int u = 0; u < 4; u++) {
#pragma unroll
        for (int o = 1; o < 16; o <<= 1)
            rsp[u] += __shfl_xor_sync(0xffffffffu, rsp[u], o);
        rsp[u] = 1.f / rsp[u];
    }
    // ---- H normalized -> Pt transposed ----
    {
        float hv[4][4];
#pragma unroll
        for (int u = 0; u < 4; u++) {
            float2 p0 = unpk(acc3[u][0]), p1 = unpk(acc3[u][1]);
            hv[u][0] = p0.x * rsp[u]; hv[u][1] = p0.y * rsp[u];
            hv[u][2] = p1.x * rsp[u]; hv[u][3] = p1.y * rsp[u];
        }
#pragma unroll
        for (int v = 0; v < 4; v++)
            *(float4*)&Pt[pb + v * 96] =
                make_float4(hv[0][v], hv[1][v], hv[2][v], hv[3][v]);
    }
    cp_wait<0>();
    __syncthreads();

    // ---- phase 4: out = relu(H W + b) ----
    ull a4c[4][2];
    {
        ulonglong2 bo = *(const ulonglong2*)&bsO[c0];
#pragma unroll
        for (int u = 0; u < 4; u++) { a4c[u][0] = bo.x; a4c[u][1] = bo.y; }
    }
#pragma unroll 8
    for (int d = 0; d < 64; d++) {
        float4 a4 = *(const float4*)&Pt[d * 96 + ((d >> 2) & 7) * 4 + r0];
        ulonglong2 wv = *(const ulonglong2*)&eb0[d * 64 + c0];
        ull d0 = dup2(a4.x), d1 = dup2(a4.y), d2 = dup2(a4.z), d3 = dup2(a4.w);
        fma2(a4c[0][0], d0, wv.x); fma2(a4c[0][1], d0, wv.y);
        fma2(a4c[1][0], d1, wv.x); fma2(a4c[1][1], d1, wv.y);
        fma2(a4c[2][0], d2, wv.x); fma2(a4c[2][1], d2, wv.y);
        fma2(a4c[3][0], d3, wv.x); fma2(a4c[3][1], d3, wv.y);
    }
#pragma unroll
    for (int u = 0; u < 4; u++) {
        float2 p0 = unpk(a4c[u][0]), p1 = unpk(a4c[u][1]);
        float4 o = make_float4(fmaxf(p0.x, 0.f), fmaxf(p0.y, 0.f),
                               fmaxf(p1.x, 0.f), fmaxf(p1.y, 0.f));
        *(float4*)&out[((size_t)(b * Nn + i0 + r0 + u) * Tt + t) * Hh + c0] = o;
    }
}

// ============================================================================
extern "C" void kernel_launch(void* const* d_in, const int* in_sizes, int n_in,
                              void* d_out, int out_size) {
    const float* x  = (const float*)d_in[0];
    const float* W1 = (const float*)d_in[1];
    const float* b1 = (const float*)d_in[2];
    const float* W2 = (const float*)d_in[3];
    const float* b2 = (const float*)d_in[4];
    const float* W  = (const float*)d_in[5];
    const float* bias = (const float*)d_in[6];
    float* out = (float*)d_out;

    const int smemP = 17216 * 4;  // 68,864 B
    const int smemM = 27008 * 4;  // 108,032 B
    cudaFuncSetAttribute(gcn_proj, cudaFuncAttributeMaxDynamicSharedMemorySize, smemP);
    cudaFuncSetAttribute(gcn_main, cudaFuncAttributeMaxDynamicSharedMemorySize, smemM);

    gcn_proj<<<Bb * Tt * 2, 256, smemP>>>(x, W2, b2);
    gcn_main<<<Bb * Tt * 8, 256, smemM>>>(x, W1, b1, W, bias, out);
}

// round 5
// speedup vs baseline: 1.4717x; 1.4697x over previous
#include <cuda_runtime.h>

#define Bb 16
#define Nn 512
#define Tt 24
#define Dd 64
#define Ee 64
#define Hh 64
#define TSTR 68   // transposed-buffer row stride (64 + 4 pad)

// E2 scratch, k-major [B,T,E,N]
__device__ float g_e2t[Bb * Tt * Ee * Nn];

typedef unsigned long long ull;

// ---------- helpers ----------
__device__ __forceinline__ ull dup2(float a) {
    ull r;
    asm("mov.b64 %0, {%1, %1};" : "=l"(r) : "f"(a));
    return r;
}
__device__ __forceinline__ void fma2(ull& c, ull a, ull b) {
    asm("fma.rn.f32x2 %0, %1, %2, %0;" : "+l"(c) : "l"(a), "l"(b));
}
__device__ __forceinline__ float2 unpk(ull v) {
    float2 r;
    asm("mov.b64 {%0, %1}, %2;" : "=f"(r.x), "=f"(r.y) : "l"(v));
    return r;
}
__device__ __forceinline__ void cp16(float* s, const float* g) {
    unsigned int sa = (unsigned int)__cvta_generic_to_shared(s);
    asm volatile("cp.async.cg.shared.global [%0], [%1], 16;" ::"r"(sa), "l"(g));
}
__device__ __forceinline__ void cp_commit() { asm volatile("cp.async.commit_group;"); }
template <int N>
__device__ __forceinline__ void cp_wait() {
    asm volatile("cp.async.wait_group %0;" ::"n"(N));
}

// unpack acc[8][2] (8 rows x 4 cols of f32x2 pairs) into pv[8][4]
__device__ __forceinline__ void unpack84(const ull (*acc)[2], float (*pv)[4]) {
#pragma unroll
    for (int u = 0; u < 8; u++) {
        float2 p0 = unpk(acc[u][0]), p1 = unpk(acc[u][1]);
        pv[u][0] = p0.x; pv[u][1] = p0.y; pv[u][2] = p1.x; pv[u][3] = p1.y;
    }
}
// store pv[8][4] transposed: base[(c0+v)*stride + r0 + {0,4}]
__device__ __forceinline__ void store_t(float* base, int c0, int r0,
                                        const float (*pv)[4], int stride) {
#pragma unroll
    for (int v = 0; v < 4; v++) {
        *(float4*)&base[(c0 + v) * stride + r0] =
            make_float4(pv[0][v], pv[1][v], pv[2][v], pv[3][v]);
        *(float4*)&base[(c0 + v) * stride + r0 + 4] =
            make_float4(pv[4][v], pv[5][v], pv[6][v], pv[7][v]);
    }
}

// ============================================================================
// Kernel P: E2^T = (x@W2+b2)^T stored k-major [B,T,E,N].
// grid = B*T*8 (one 64-row n-tile per block), 128 threads, 8x4 thread tile.
// ============================================================================
__global__ void __launch_bounds__(128, 4)
gcn_proj(const float* __restrict__ x, const float* __restrict__ W2,
         const float* __restrict__ b2) {
    extern __shared__ float sm[];
    float* xb = sm;          // 4096  x tile [n][d]
    float* Ws = sm + 4096;   // 4096  W2 [d][e]
    float* bs = sm + 8192;   // 64

    const int tid = threadIdx.x;
    const int blk = blockIdx.x;
    const int nt = blk & 7, bt = blk >> 3;
    const int t = bt % Tt, b = bt / Tt;
    const int n0 = nt * 64;
    const float* xg = x + ((size_t)(b * Nn + n0) * Tt + t) * Dd;

#pragma unroll
    for (int i = 0; i < 8; i++) {
        int ch = tid + 128 * i, row = ch >> 4, col = (ch & 15) * 4;
        cp16(&xb[row * 64 + col], &xg[(size_t)row * (Tt * Dd) + col]);
        cp16(&Ws[ch * 4], &W2[ch * 4]);
    }
    if (tid < 16) cp16(&bs[tid * 4], &b2[tid * 4]);
    cp_commit();
    cp_wait<0>();
    __syncthreads();

    const int r0 = (tid >> 4) * 8, c0 = (tid & 15) * 4;
    ull acc[8][2];
    {
        ulonglong2 bb = *(const ulonglong2*)&bs[c0];
#pragma unroll
        for (int u = 0; u < 8; u++) { acc[u][0] = bb.x; acc[u][1] = bb.y; }
    }
#pragma unroll 8
    for (int d = 0; d < 64; d++) {
        ulonglong2 wv = *(const ulonglong2*)&Ws[d * 64 + c0];
#pragma unroll
        for (int u = 0; u < 8; u++) {
            ull ad = dup2(xb[(r0 + u) * 64 + d]);
            fma2(acc[u][0], ad, wv.x);
            fma2(acc[u][1], ad, wv.y);
        }
    }
    float pv[8][4];
    unpack84(acc, pv);
    float* gout = g_e2t + (size_t)(b * Tt + t) * Ee * Nn + n0;
#pragma unroll
    for (int v = 0; v < 4; v++) {
        *(float4*)&gout[(size_t)(c0 + v) * Nn + r0] =
            make_float4(pv[0][v], pv[1][v], pv[2][v], pv[3][v]);
        *(float4*)&gout[(size_t)(c0 + v) * Nn + r0 + 4] =
            make_float4(pv[4][v], pv[5][v], pv[6][v], pv[7][v]);
    }
}

// ============================================================================
// Kernel M: per (b,t,i-tile of 64): E1=x_i@W1+b1; stream 8 j-tiles:
//   S=E1 E2^T, P=exp(relu(S)), H += P X; out = relu((H/rs) W + b)
// grid = B*T*8, 128 threads (8x4 tile), 3 CTAs/SM.
// ============================================================================
__global__ void __launch_bounds__(128, 3)
gcn_main(const float* __restrict__ x, const float* __restrict__ W1,
         const float* __restrict__ b1, const float* __restrict__ W,
         const float* __restrict__ bias, float* __restrict__ out) {
    extern __shared__ float sm[];
    float* e1s = sm;           // 4352  E1^T [e][i] stride 68
    float* Pt  = sm + 4352;    // 4352  P^T/H^T [j|d][i] stride 68 (also W1 staging)
    float* eb  = sm + 8704;    // 4096  e2 tile [e][j]   (also x_i staging, W in ph4)
    float* xb  = sm + 12800;   // 4096  x tile [j][d]
    float* bs1 = sm + 16896;   // 64
    float* bsO = sm + 16960;   // 64    total 17024 floats

    const int tid = threadIdx.x;
    const int blk = blockIdx.x;
    const int it = blk & 7, bt = blk >> 3;
    const int t = bt % Tt, b = bt / Tt;
    const int i0 = it * 64;

    const float* e2g = g_e2t + (size_t)(b * Tt + t) * Ee * Nn;
    const float* xg = x + ((size_t)b * Nn * Tt + t) * Dd;

    const int r0 = (tid >> 4) * 8, c0 = (tid & 15) * 4;

    // ---- prologue group A: x_i -> eb, W1 -> Pt, biases ----
#pragma unroll
    for (int i = 0; i < 8; i++) {
        int ch = tid + 128 * i, row = ch >> 4, col = (ch & 15) * 4;
        cp16(&eb[row * 64 + col], &xg[(size_t)(i0 + row) * (Tt * Dd) + col]);
        cp16(&Pt[ch * 4], &W1[ch * 4]);
    }
    if (tid < 16) cp16(&bs1[tid * 4], &b1[tid * 4]);
    else if (tid < 32) cp16(&bsO[(tid - 16) * 4], &bias[(tid - 16) * 4]);
    cp_commit();
    cp_wait<0>();
    __syncthreads();

    // ---- GEMM0: E1 = x_i @ W1 + b1 -> e1s transposed ----
    {
        ull a0[8][2];
        ulonglong2 bb = *(const ulonglong2*)&bs1[c0];
#pragma unroll
        for (int u = 0; u < 8; u++) { a0[u][0] = bb.x; a0[u][1] = bb.y; }
#pragma unroll 8
        for (int d = 0; d < 64; d++) {
            ulonglong2 wv = *(const ulonglong2*)&Pt[d * 64 + c0];
#pragma unroll
            for (int u = 0; u < 8; u++) {
                ull ad = dup2(eb[(r0 + u) * 64 + d]);
                fma2(a0[u][0], ad, wv.x);
                fma2(a0[u][1], ad, wv.y);
            }
        }
        float pv[8][4];
        unpack84(a0, pv);
        __syncthreads();  // all W1/x_i reads done before overwriting Pt/eb users
        store_t(e1s, c0, r0, pv, TSTR);
    }
    __syncthreads();  // e1s visible; eb,Pt free

    // kick off pipeline: e2(0) then x(0) as separate groups
#pragma unroll
    for (int i = 0; i < 8; i++) {
        int ch = tid + 128 * i, row = ch >> 4, col = (ch & 15) * 4;
        cp16(&eb[row * 64 + col], &e2g[row * Nn + col]);
    }
    cp_commit();
#pragma unroll
    for (int i = 0; i < 8; i++) {
        int ch = tid + 128 * i, row = ch >> 4, col = (ch & 15) * 4;
        cp16(&xb[row * 64 + col], &xg[(size_t)row * (Tt * Dd) + col]);
    }
    cp_commit();

    float rsp[8] = {0, 0, 0, 0, 0, 0, 0, 0};
    ull acc3[8][2];
#pragma unroll
    for (int u = 0; u < 8; u++) { acc3[u][0] = 0ull; acc3[u][1] = 0ull; }

    for (int jt = 0; jt < 8; jt++) {
        cp_wait<1>();       // e2(jt) ready
        __syncthreads();

        // ---- GEMM1: S-tile = E1 E2^T ----
        ull acc[8][2];
#pragma unroll
        for (int u = 0; u < 8; u++) { acc[u][0] = 0ull; acc[u][1] = 0ull; }
#pragma unroll 8
        for (int e = 0; e < 64; e++) {
            float4 alo = *(const float4*)&e1s[e * TSTR + r0];
            float4 ahi = *(const float4*)&e1s[e * TSTR + r0 + 4];
            ulonglong2 bv = *(const ulonglong2*)&eb[e * 64 + c0];
            ull d0 = dup2(alo.x), d1 = dup2(alo.y), d2 = dup2(alo.z), d3 = dup2(alo.w);
            ull d4 = dup2(ahi.x), d5 = dup2(ahi.y), d6 = dup2(ahi.z), d7 = dup2(ahi.w);
            fma2(acc[0][0], d0, bv.x); fma2(acc[0][1], d0, bv.y);
            fma2(acc[1][0], d1, bv.x); fma2(acc[1][1], d1, bv.y);
            fma2(acc[2][0], d2, bv.x); fma2(acc[2][1], d2, bv.y);
            fma2(acc[3][0], d3, bv.x); fma2(acc[3][1], d3, bv.y);
            fma2(acc[4][0], d4, bv.x); fma2(acc[4][1], d4, bv.y);
            fma2(acc[5][0], d5, bv.x); fma2(acc[5][1], d5, bv.y);
            fma2(acc[6][0], d6, bv.x); fma2(acc[6][1], d6, bv.y);
            fma2(acc[7][0], d7, bv.x); fma2(acc[7][1], d7, bv.y);
        }
        // ---- exp(relu) max-free, partial row sums, P^T store ----
        float pv[8][4];
        unpack84(acc, pv);
#pragma unroll
        for (int u = 0; u < 8; u++) {
#pragma unroll
            for (int v = 0; v < 4; v++) {
                pv[u][v] = __expf(fminf(fmaxf(pv[u][v], 0.f), 80.f));
            }
            rsp[u] += (pv[u][0] + pv[u][1]) + (pv[u][2] + pv[u][3]);
        }
        store_t(Pt, c0, r0, pv, TSTR);
        __syncthreads();    // Pt complete; eb free

        // prefetch next e2 (or W on last iter) into eb
        if (jt < 7) {
            const float* src = e2g + (jt + 1) * 64;
#pragma unroll
            for (int i = 0; i < 8; i++) {
                int ch = tid + 128 * i, row = ch >> 4, col = (ch & 15) * 4;
                cp16(&eb[row * 64 + col], &src[row * Nn + col]);
            }
        } else {
#pragma unroll
            for (int i = 0; i < 8; i++) {
                int ch = tid + 128 * i;
                cp16(&eb[ch * 4], &W[ch * 4]);
            }
        }
        cp_commit();
        cp_wait<1>();       // x(jt) ready
        __syncthreads();

        // ---- GEMM2: H += P X ----
#pragma unroll 8
        for (int j = 0; j < 64; j++) {
            float4 alo = *(const float4*)&Pt[j * TSTR + r0];
            float4 ahi = *(const float4*)&Pt[j * TSTR + r0 + 4];
            ulonglong2 xv = *(const ulonglong2*)&xb[j * 64 + c0];
            ull d0 = dup2(alo.x), d1 = dup2(alo.y), d2 = dup2(alo.z), d3 = dup2(alo.w);
            ull d4 = dup2(ahi.x), d5 = dup2(ahi.y), d6 = dup2(ahi.z), d7 = dup2(ahi.w);
            fma2(acc3[0][0], d0, xv.x); fma2(acc3[0][1], d0, xv.y);
            fma2(acc3[1][0], d1, xv.x); fma2(acc3[1][1], d1, xv.y);
            fma2(acc3[2][0], d2, xv.x); fma2(acc3[2][1], d2, xv.y);
            fma2(acc3[3][0], d3, xv.x); fma2(acc3[3][1], d3, xv.y);
            fma2(acc3[4][0], d4, xv.x); fma2(acc3[4][1], d4, xv.y);
            fma2(acc3[5][0], d5, xv.x); fma2(acc3[5][1], d5, xv.y);
            fma2(acc3[6][0], d6, xv.x); fma2(acc3[6][1], d6, xv.y);
            fma2(acc3[7][0], d7, xv.x); fma2(acc3[7][1], d7, xv.y);
        }
        __syncthreads();    // xb free

        if (jt < 7) {
            const float* src = xg + (size_t)(jt + 1) * 64 * (Tt * Dd);
#pragma unroll
            for (int i = 0; i < 8; i++) {
                int ch = tid + 128 * i, row = ch >> 4, col = (ch & 15) * 4;
                cp16(&xb[row * 64 + col], &src[(size_t)row * (Tt * Dd) + col]);
            }
            cp_commit();
        }
    }

    // ---- finalize row sums (16-lane butterfly; halves independent) ----
#pragma unroll
    for (int u = 0; u < 8; u++) {
#pragma unroll
        for (int o = 1; o < 16; o <<= 1)
            rsp[u] += __shfl_xor_sync(0xffffffffu, rsp[u], o);
        rsp[u] = 1.f / rsp[u];
    }
    // ---- H normalized -> Pt transposed (H^T [d][i]) ----
    {
        float hv[8][4];
        unpack84(acc3, hv);
#pragma unroll
        for (int u = 0; u < 8; u++) {
#pragma unroll
            for (int v = 0; v < 4; v++) hv[u][v] *= rsp[u];
        }
        store_t(Pt, c0, r0, hv, TSTR);
    }
    cp_wait<0>();           // W in eb
    __syncthreads();

    // ---- GEMM3: out = relu(H W + b) ----
    ull a4[8][2];
    {
        ulonglong2 bo = *(const ulonglong2*)&bsO[c0];
#pragma unroll
        for (int u = 0; u < 8; u++) { a4[u][0] = bo.x; a4[u][1] = bo.y; }
    }
#pragma unroll 8
    for (int d = 0; d < 64; d++) {
        float4 alo = *(const float4*)&Pt[d * TSTR + r0];
        float4 ahi = *(const float4*)&Pt[d * TSTR + r0 + 4];
        ulonglong2 wv = *(const ulonglong2*)&eb[d * 64 + c0];
        ull d0 = dup2(alo.x), d1 = dup2(alo.y), d2 = dup2(alo.z), d3 = dup2(alo.w);
        ull d4 = dup2(ahi.x), d5 = dup2(ahi.y), d6 = dup2(ahi.z), d7 = dup2(ahi.w);
        fma2(a4[0][0], d0, wv.x); fma2(a4[0][1], d0, wv.y);
        fma2(a4[1][0], d1, wv.x); fma2(a4[1][1], d1, wv.y);
        fma2(a4[2][0], d2, wv.x); fma2(a4[2][1], d2, wv.y);
        fma2(a4[3][0], d3, wv.x); fma2(a4[3][1], d3, wv.y);
        fma2(a4[4][0], d4, wv.x); fma2(a4[4][1], d4, wv.y);
        fma2(a4[5][0], d5, wv.x); fma2(a4[5][1], d5, wv.y);
        fma2(a4[6][0], d6, wv.x); fma2(a4[6][1], d6, wv.y);
        fma2(a4[7][0], d7, wv.x); fma2(a4[7][1], d7, wv.y);
    }
    float ov[8][4];
    unpack84(a4, ov);
#pragma unroll
    for (int u = 0; u < 8; u++) {
        float4 o = make_float4(fmaxf(ov[u][0], 0.f), fmaxf(ov[u][1], 0.f),
                               fmaxf(ov[u][2], 0.f), fmaxf(ov[u][3], 0.f));
        *(float4*)&out[((size_t)(b * Nn + i0 + r0 + u) * Tt + t) * Hh + c0] = o;
    }
}

// ============================================================================
extern "C" void kernel_launch(void* const* d_in, const int* in_sizes, int n_in,
                              void* d_out, int out_size) {
    const float* x  = (const float*)d_in[0];
    const float* W1 = (const float*)d_in[1];
    const float* b1 = (const float*)d_in[2];
    const float* W2 = (const float*)d_in[3];
    const float* b2 = (const float*)d_in[4];
    const float* W  = (const float*)d_in[5];
    const float* bias = (const float*)d_in[6];
    float* out = (float*)d_out;

    const int smemP = 8256 * 4;    // 33,024 B
    const int smemM = 17024 * 4;   // 68,096 B
    cudaFuncSetAttribute(gcn_proj, cudaFuncAttributeMaxDynamicSharedMemorySize, smemP);
    cudaFuncSetAttribute(gcn_main, cudaFuncAttributeMaxDynamicSharedMemorySize, smemM);

    gcn_proj<<<Bb * Tt * 8, 128, smemP>>>(x, W2, b2);
    gcn_main<<<Bb * Tt * 8, 128, smemM>>>(x, W1, b1, W, bias, out);
}

// round 6
// speedup vs baseline: 1.5620x; 1.0613x over previous
#include <cuda_runtime.h>

#define Bb 16
#define Nn 512
#define Tt 24
#define Dd 64
#define Ee 64
#define Hh 64
#define TSTR 68   // transposed-buffer row stride (64 + 4 pad)

// E2 scratch, k-major [B,T,E,N]
__device__ float g_e2t[Bb * Tt * Ee * Nn];

typedef unsigned long long ull;

// ---------- helpers ----------
__device__ __forceinline__ ull dup2(float a) {
    ull r;
    asm("mov.b64 %0, {%1, %1};" : "=l"(r) : "f"(a));
    return r;
}
__device__ __forceinline__ void fma2(ull& c, ull a, ull b) {
    asm("fma.rn.f32x2 %0, %1, %2, %0;" : "+l"(c) : "l"(a), "l"(b));
}
__device__ __forceinline__ float2 unpk(ull v) {
    float2 r;
    asm("mov.b64 {%0, %1}, %2;" : "=f"(r.x), "=f"(r.y) : "l"(v));
    return r;
}
__device__ __forceinline__ void cp16(float* s, const float* g) {
    unsigned int sa = (unsigned int)__cvta_generic_to_shared(s);
    asm volatile("cp.async.cg.shared.global [%0], [%1], 16;" ::"r"(sa), "l"(g));
}
__device__ __forceinline__ void cp_commit() { asm volatile("cp.async.commit_group;"); }
template <int N>
__device__ __forceinline__ void cp_wait() {
    asm volatile("cp.async.wait_group %0;" ::"n"(N));
}

// 16 fma2: acc[p][v] (+= a-pair p * dup(b col v)); pairs cover rows 2p,2p+1
__device__ __forceinline__ void mma_pairs(ull (*acc)[4], const float* a_t, int astride,
                                          const float* bm, int k, int r0, int c0) {
    ulonglong2 alo = *(const ulonglong2*)&a_t[k * astride + r0];
    ulonglong2 ahi = *(const ulonglong2*)&a_t[k * astride + r0 + 4];
    float4 bq = *(const float4*)&bm[k * 64 + c0];
    ull b0 = dup2(bq.x), b1 = dup2(bq.y), b2 = dup2(bq.z), b3 = dup2(bq.w);
    fma2(acc[0][0], alo.x, b0); fma2(acc[0][1], alo.x, b1);
    fma2(acc[0][2], alo.x, b2); fma2(acc[0][3], alo.x, b3);
    fma2(acc[1][0], alo.y, b0); fma2(acc[1][1], alo.y, b1);
    fma2(acc[1][2], alo.y, b2); fma2(acc[1][3], alo.y, b3);
    fma2(acc[2][0], ahi.x, b0); fma2(acc[2][1], ahi.x, b1);
    fma2(acc[2][2], ahi.x, b2); fma2(acc[2][3], ahi.x, b3);
    fma2(acc[3][0], ahi.y, b0); fma2(acc[3][1], ahi.y, b1);
    fma2(acc[3][2], ahi.y, b2); fma2(acc[3][3], ahi.y, b3);
}

// unpack pair-accs acc[4][4] -> pv[8][4] (row-major scalars)
__device__ __forceinline__ void unpack_pairs(const ull (*acc)[4], float (*pv)[4]) {
#pragma unroll
    for (int p = 0; p < 4; p++)
#pragma unroll
        for (int v = 0; v < 4; v++) {
            float2 f = unpk(acc[p][v]);
            pv[2 * p][v] = f.x;
            pv[2 * p + 1][v] = f.y;
        }
}

// unpack col-pair accs acc[8][2] (8 rows x 4 cols) -> pv[8][4]
__device__ __forceinline__ void unpack84(const ull (*acc)[2], float (*pv)[4]) {
#pragma unroll
    for (int u = 0; u < 8; u++) {
        float2 p0 = unpk(acc[u][0]), p1 = unpk(acc[u][1]);
        pv[u][0] = p0.x; pv[u][1] = p0.y; pv[u][2] = p1.x; pv[u][3] = p1.y;
    }
}

// store pv[8][4] transposed: base[(c0+v)*stride + r0 + {0,4}]
__device__ __forceinline__ void store_t(float* base, int c0, int r0,
                                        const float (*pv)[4], int stride) {
#pragma unroll
    for (int v = 0; v < 4; v++) {
        *(float4*)&base[(c0 + v) * stride + r0] =
            make_float4(pv[0][v], pv[1][v], pv[2][v], pv[3][v]);
        *(float4*)&base[(c0 + v) * stride + r0 + 4] =
            make_float4(pv[4][v], pv[5][v], pv[6][v], pv[7][v]);
    }
}

// ============================================================================
// Kernel P: E2^T = (x@W2+b2)^T stored k-major [B,T,E,N].
// grid = B*T*8 (one 64-row n-tile per block), 128 threads, 8x4 thread tile.
// ============================================================================
__global__ void __launch_bounds__(128, 4)
gcn_proj(const float* __restrict__ x, const float* __restrict__ W2,
         const float* __restrict__ b2) {
    extern __shared__ float sm[];
    float* xb = sm;          // 4096  x tile [n][d]
    float* Ws = sm + 4096;   // 4096  W2 [d][e]
    float* bs = sm + 8192;   // 64

    const int tid = threadIdx.x;
    const int blk = blockIdx.x;
    const int nt = blk & 7, bt = blk >> 3;
    const int t = bt % Tt, b = bt / Tt;
    const int n0 = nt * 64;
    const float* xg = x + ((size_t)(b * Nn + n0) * Tt + t) * Dd;

#pragma unroll
    for (int i = 0; i < 8; i++) {
        int ch = tid + 128 * i, row = ch >> 4, col = (ch & 15) * 4;
        cp16(&xb[row * 64 + col], &xg[(size_t)row * (Tt * Dd) + col]);
        cp16(&Ws[ch * 4], &W2[ch * 4]);
    }
    if (tid < 16) cp16(&bs[tid * 4], &b2[tid * 4]);
    cp_commit();
    cp_wait<0>();
    __syncthreads();

    const int r0 = (tid >> 4) * 8, c0 = (tid & 15) * 4;
    ull acc[8][2];
    {
        ulonglong2 bb = *(const ulonglong2*)&bs[c0];
#pragma unroll
        for (int u = 0; u < 8; u++) { acc[u][0] = bb.x; acc[u][1] = bb.y; }
    }
#pragma unroll 8
    for (int d = 0; d < 64; d++) {
        ulonglong2 wv = *(const ulonglong2*)&Ws[d * 64 + c0];
#pragma unroll
        for (int u = 0; u < 8; u++) {
            ull ad = dup2(xb[(r0 + u) * 64 + d]);
            fma2(acc[u][0], ad, wv.x);
            fma2(acc[u][1], ad, wv.y);
        }
    }
    float pv[8][4];
    unpack84(acc, pv);
    float* gout = g_e2t + (size_t)(b * Tt + t) * Ee * Nn + n0;
#pragma unroll
    for (int v = 0; v < 4; v++) {
        *(float4*)&gout[(size_t)(c0 + v) * Nn + r0] =
            make_float4(pv[0][v], pv[1][v], pv[2][v], pv[3][v]);
        *(float4*)&gout[(size_t)(c0 + v) * Nn + r0 + 4] =
            make_float4(pv[4][v], pv[5][v], pv[6][v], pv[7][v]);
    }
}

// ============================================================================
// Kernel M: per (b,t,i-tile of 64): E1=x_i@W1+b1; stream 8 j-tiles:
//   S=E1 E2^T, P=exp(relu(S)), H += P X; out = relu((H/rs) W + b)
// grid = B*T*8, 128 threads, 2x2 warps over 64x64, pair-packed accumulators.
// ============================================================================
__global__ void __launch_bounds__(128, 3)
gcn_main(const float* __restrict__ x, const float* __restrict__ W1,
         const float* __restrict__ b1, const float* __restrict__ W,
         const float* __restrict__ bias, float* __restrict__ out) {
    extern __shared__ float sm[];
    float* e1s   = sm;           // 4352  E1^T [e][i] stride 68
    float* Pt    = sm + 4352;    // 4352  P^T/H^T [j|d][i] stride 68 (also W1 staging)
    float* eb    = sm + 8704;    // 4096  e2 tile [e][j] (also x_i staging, W in ph4)
    float* xb    = sm + 12800;   // 4096  x tile [j][d]
    float* bs1   = sm + 16896;   // 64
    float* bsO   = sm + 16960;   // 64
    float* rpart = sm + 17024;   // 128  row-sum partials [warpC][row]

    const int tid = threadIdx.x;
    const int blk = blockIdx.x;
    const int it = blk & 7, bt = blk >> 3;
    const int t = bt % Tt, b = bt / Tt;
    const int i0 = it * 64;

    const float* e2g = g_e2t + (size_t)(b * Tt + t) * Ee * Nn;
    const float* xg = x + ((size_t)b * Nn * Tt + t) * Dd;

    const int warp = tid >> 5, lane = tid & 31;
    const int wC = warp & 1;
    const int r0 = (warp >> 1) * 32 + (lane >> 3) * 8;
    const int c0 = wC * 32 + (lane & 7) * 4;

    // ---- prologue group A: x_i -> eb, W1 -> Pt, biases ----
#pragma unroll
    for (int i = 0; i < 8; i++) {
        int ch = tid + 128 * i, row = ch >> 4, col = (ch & 15) * 4;
        cp16(&eb[row * 64 + col], &xg[(size_t)(i0 + row) * (Tt * Dd) + col]);
        cp16(&Pt[ch * 4], &W1[ch * 4]);
    }
    if (tid < 16) cp16(&bs1[tid * 4], &b1[tid * 4]);
    else if (tid < 32) cp16(&bsO[(tid - 16) * 4], &bias[(tid - 16) * 4]);
    cp_commit();
    cp_wait<0>();
    __syncthreads();

    // ---- GEMM0: E1 = x_i @ W1 + b1 -> e1s transposed (dup-a style) ----
    {
        ull a0[8][2];
        ulonglong2 bb = *(const ulonglong2*)&bs1[c0];
#pragma unroll
        for (int u = 0; u < 8; u++) { a0[u][0] = bb.x; a0[u][1] = bb.y; }
#pragma unroll 8
        for (int d = 0; d < 64; d++) {
            ulonglong2 wv = *(const ulonglong2*)&Pt[d * 64 + c0];
#pragma unroll
            for (int u = 0; u < 8; u++) {
                ull ad = dup2(eb[(r0 + u) * 64 + d]);
                fma2(a0[u][0], ad, wv.x);
                fma2(a0[u][1], ad, wv.y);
            }
        }
        float pv[8][4];
        unpack84(a0, pv);
        __syncthreads();  // all W1/x_i reads done before overwriting Pt/eb
        store_t(e1s, c0, r0, pv, TSTR);
    }
    __syncthreads();  // e1s visible; eb,Pt free

    // kick off pipeline: e2(0) then x(0) as separate groups
#pragma unroll
    for (int i = 0; i < 8; i++) {
        int ch = tid + 128 * i, row = ch >> 4, col = (ch & 15) * 4;
        cp16(&eb[row * 64 + col], &e2g[row * Nn + col]);
    }
    cp_commit();
#pragma unroll
    for (int i = 0; i < 8; i++) {
        int ch = tid + 128 * i, row = ch >> 4, col = (ch & 15) * 4;
        cp16(&xb[row * 64 + col], &xg[(size_t)row * (Tt * Dd) + col]);
    }
    cp_commit();

    float rsp[8] = {0, 0, 0, 0, 0, 0, 0, 0};
    ull acc3[4][4];
#pragma unroll
    for (int p = 0; p < 4; p++)
#pragma unroll
        for (int v = 0; v < 4; v++) acc3[p][v] = 0ull;

    for (int jt = 0; jt < 8; jt++) {
        cp_wait<1>();  // e2(jt) ready
        __syncthreads();

        // ---- GEMM1: S-tile = E1 E2^T (pair-packed over rows) ----
        ull acc[4][4];
#pragma unroll
        for (int p = 0; p < 4; p++)
#pragma unroll
            for (int v = 0; v < 4; v++) acc[p][v] = 0ull;
#pragma unroll 8
        for (int e = 0; e < 64; e++) mma_pairs(acc, e1s, TSTR, eb, e, r0, c0);

        // ---- exp(relu) max-free, partial row sums, P^T store ----
        float pv[8][4];
        unpack_pairs(acc, pv);
#pragma unroll
        for (int u = 0; u < 8; u++) {
#pragma unroll
            for (int v = 0; v < 4; v++)
                pv[u][v] = __expf(fminf(fmaxf(pv[u][v], 0.f), 80.f));
            rsp[u] += (pv[u][0] + pv[u][1]) + (pv[u][2] + pv[u][3]);
        }
        store_t(Pt, c0, r0, pv, TSTR);
        __syncthreads();  // Pt complete; eb free

        // prefetch next e2 (or W on last iter) into eb
        if (jt < 7) {
            const float* src = e2g + (jt + 1) * 64;
#pragma unroll
            for (int i = 0; i < 8; i++) {
                int ch = tid + 128 * i, row = ch >> 4, col = (ch & 15) * 4;
                cp16(&eb[row * 64 + col], &src[row * Nn + col]);
            }
        } else {
#pragma unroll
            for (int i = 0; i < 8; i++) {
                int ch = tid + 128 * i;
                cp16(&eb[ch * 4], &W[ch * 4]);
            }
        }
        cp_commit();
        cp_wait<1>();  // x(jt) ready
        __syncthreads();

        // ---- GEMM2: H += P X ----
#pragma unroll 8
        for (int j = 0; j < 64; j++) mma_pairs(acc3, Pt, TSTR, xb, j, r0, c0);
        __syncthreads();  // xb free

        if (jt < 7) {
            const float* src = xg + (size_t)(jt + 1) * 64 * (Tt * Dd);
#pragma unroll
            for (int i = 0; i < 8; i++) {
                int ch = tid + 128 * i, row = ch >> 4, col = (ch & 15) * 4;
                cp16(&xb[row * 64 + col], &src[(size_t)row * (Tt * Dd) + col]);
            }
            cp_commit();
        }
    }

    // ---- finalize row sums: 8-lane butterfly, then cross-warpC combine ----
#pragma unroll
    for (int u = 0; u < 8; u++) {
#pragma unroll
        for (int o = 1; o < 8; o <<= 1)
            rsp[u] += __shfl_xor_sync(0xffffffffu, rsp[u], o);
    }
    if ((lane & 7) == 0) {
#pragma unroll
        for (int u = 0; u < 8; u++) rpart[wC * 64 + r0 + u] = rsp[u];
    }
    __syncthreads();

    // ---- H normalized -> Pt transposed (H^T [d][i]) ----
    {
        float hv[8][4];
        unpack_pairs(acc3, hv);
#pragma unroll
        for (int u = 0; u < 8; u++) {
            float inv = 1.f / (rpart[r0 + u] + rpart[64 + r0 + u]);
#pragma unroll
            for (int v = 0; v < 4; v++) hv[u][v] *= inv;
        }
        store_t(Pt, c0, r0, hv, TSTR);
    }
    cp_wait<0>();  // W in eb
    __syncthreads();

    // ---- GEMM3: out = relu(H W + b) ----
    ull a4[4][4];
    {
#pragma unroll
        for (int v = 0; v < 4; v++) {
            ull bv = dup2(bsO[c0 + v]);
#pragma unroll
            for (int p = 0; p < 4; p++) a4[p][v] = bv;
        }
    }
#pragma unroll 8
    for (int d = 0; d < 64; d++) mma_pairs(a4, Pt, TSTR, eb, d, r0, c0);

    float ov[8][4];
    unpack_pairs(a4, ov);
#pragma unroll
    for (int u = 0; u < 8; u++) {
        float4 o = make_float4(fmaxf(ov[u][0], 0.f), fmaxf(ov[u][1], 0.f),
                               fmaxf(ov[u][2], 0.f), fmaxf(ov[u][3], 0.f));
        *(float4*)&out[((size_t)(b * Nn + i0 + r0 + u) * Tt + t) * Hh + c0] = o;
    }
}

// ============================================================================
extern "C" void kernel_launch(void* const* d_in, const int* in_sizes, int n_in,
                              void* d_out, int out_size) {
    const float* x  = (const float*)d_in[0];
    const float* W1 = (const float*)d_in[1];
    const float* b1 = (const float*)d_in[2];
    const float* W2 = (const float*)d_in[3];
    const float* b2 = (const float*)d_in[4];
    const float* W  = (const float*)d_in[5];
    const float* bias = (const float*)d_in[6];
    float* out = (float*)d_out;

    const int smemP = 8256 * 4;    // 33,024 B
    const int smemM = 17152 * 4;   // 68,608 B
    cudaFuncSetAttribute(gcn_proj, cudaFuncAttributeMaxDynamicSharedMemorySize, smemP);
    cudaFuncSetAttribute(gcn_main, cudaFuncAttributeMaxDynamicSharedMemorySize, smemM);

    gcn_proj<<<Bb * Tt * 8, 128, smemP>>>(x, W2, b2);
    gcn_main<<<Bb * Tt * 8, 128, smemM>>>(x, W1, b1, W, bias, out);
}